// round 2
// baseline (speedup 1.0000x reference)
#include <cuda_runtime.h>
#include <math.h>

// Problem constants (fixed by the reference)
#define BB 16
#define QQ 300
#define CC 256
#define NHH 8
#define DHH 32
#define SUMP 16
#define SS 8500           // 80*80+40*40+20*20+10*10
#define BQ (BB*QQ)        // 4800

// Precomputed per-(bq, h, p) gather descriptors:
//   g_idx4: 4 clamped corner indices into the value slab (level start folded in)
//   g_w4:   4 bilinear weights premultiplied by the softmax attention weight
__device__ int4   g_idx4[BQ * 128];
__device__ float4 g_w4[BQ * 128];

__device__ __constant__ int cW[4]     = {80, 40, 20, 10};
__device__ __constant__ int cStart[4] = {0, 6400, 8000, 8400};

// ---------------------------------------------------------------------------
// Kernel 1: fused GEMM (offsets + attn logits) with packed f32x2 FMAs,
// shuffle softmax, sampling-location -> gather-descriptor precompute.
// Block = 384 threads, 16 (b,q) rows per block.
//   threads [0,256):   offset columns (h,p,axis)
//   threads [256,384): attn columns (h,p)
// ---------------------------------------------------------------------------
__global__ __launch_bounds__(384) void dfine_k1(
    const float* __restrict__ hs,      // (B,Q,C)
    const float* __restrict__ refp,    // (B,Q,1,4)
    const float* __restrict__ offk,    // (C, NH*SUMP*2) col-stride 256
    const float* __restrict__ offb,    // (NH,SUMP,2)
    const float* __restrict__ attnk,   // (C, NH*SUMP) col-stride 128
    const float* __restrict__ attnb,   // (NH,SUMP)
    const float* __restrict__ nps,     // (SUMP,)
    float* __restrict__ attn_out)      // (B,Q,NH,SUMP) region of d_out
{
    // transposed A tile: sAT[c][r], padded to 20 for LDS.128-friendly layout
    __shared__ __align__(16) float sAT[CC][20];
    __shared__ float sLoc[16][256];    // sampling locations per row
    __shared__ float sAttn[16][128];   // softmax weights per row

    const int t   = threadIdx.x;       // 0..383
    const int bq0 = blockIdx.x * 16;

    // load 16 rows of hidden_states, transposed, into smem
    for (int i = t; i < 16 * CC; i += 384) {
        const int r = i >> 8, c = i & 255;
        sAT[c][r] = hs[(size_t)bq0 * CC + i];
    }
    __syncthreads();

    // ---- GEMM: 16-row accumulators as 8 packed f32x2 pairs ----
    unsigned long long acc[8];
#pragma unroll
    for (int j = 0; j < 8; j++) acc[j] = 0ULL;

    {
        const float* col = (t < 256) ? (offk + t) : (attnk + (t - 256));
        const int stride = (t < 256) ? 256 : 128;
#pragma unroll 2
        for (int c = 0; c < CC; c++) {
            float bv = __ldg(col + (size_t)c * stride);
            unsigned long long bb;
            asm("mov.b64 %0, {%1, %1};" : "=l"(bb) : "r"(__float_as_uint(bv)));
#pragma unroll
            for (int i = 0; i < 4; i++) {
                ulonglong2 v = *(const ulonglong2*)&sAT[c][4 * i];
                asm("fma.rn.f32x2 %0, %1, %2, %0;" : "+l"(acc[2*i])   : "l"(v.x), "l"(bb));
                asm("fma.rn.f32x2 %0, %1, %2, %0;" : "+l"(acc[2*i+1]) : "l"(v.y), "l"(bb));
            }
        }
    }

    // unpack accumulators -> per-row scalars
    float o[16];
#pragma unroll
    for (int j = 0; j < 8; j++) {
        unsigned u0, u1;
        asm("mov.b64 {%0, %1}, %2;" : "=r"(u0), "=r"(u1) : "l"(acc[j]));
        o[2*j]   = __uint_as_float(u0);
        o[2*j+1] = __uint_as_float(u1);
    }

    if (t < 256) {
        // offset path: bias, scale, add center -> sLoc
        const int axis   = t & 1;
        const int p      = (t >> 1) & 15;
        const float bias  = offb[t];
        const float scale = nps[p] * 0.5f;
#pragma unroll
        for (int r = 0; r < 16; r++) {
            const float* rp = refp + (size_t)(bq0 + r) * 4;
            sLoc[r][t] = fmaf((o[r] + bias) * scale, rp[2 + axis], rp[axis]);
        }
    } else {
        // attn path: shuffle softmax within 16-lane head groups
        const int cl = t - 256;
        const float bias = attnb[cl];
#pragma unroll
        for (int r = 0; r < 16; r++) {
            float lg = o[r] + bias;
            float m = lg;
#pragma unroll
            for (int s = 8; s; s >>= 1) m = fmaxf(m, __shfl_xor_sync(0xffffffffu, m, s));
            float e = __expf(lg - m);
            float sum = e;
#pragma unroll
            for (int s = 8; s; s >>= 1) sum += __shfl_xor_sync(0xffffffffu, sum, s);
            float w = e / sum;
            sAttn[r][cl] = w;
            attn_out[(size_t)(bq0 + r) * 128 + cl] = w;
        }
    }
    __syncthreads();

    // ---- gather-descriptor precompute: one thread per (h,p) ----
    if (t < 128) {
        const int h   = t >> 4;
        const int p   = t & 15;
        const int lvl = p >> 2;
        const int Wl    = cW[lvl];
        const int start = cStart[lvl];
        const float Wf  = (float)Wl;
#pragma unroll
        for (int r = 0; r < 16; r++) {
            float lx = sLoc[r][h * 32 + p * 2];
            float ly = sLoc[r][h * 32 + p * 2 + 1];
            float aw = sAttn[r][t];

            float x = lx * Wf - 0.5f;
            float y = ly * Wf - 0.5f;
            float x0f = floorf(x), y0f = floorf(y);
            float fx = x - x0f, fy = y - y0f;
            int x0 = (int)x0f, y0 = (int)y0f;
            int x1 = x0 + 1,   y1 = y0 + 1;

            bool xv0 = ((unsigned)x0 < (unsigned)Wl);
            bool xv1 = ((unsigned)x1 < (unsigned)Wl);
            bool yv0 = ((unsigned)y0 < (unsigned)Wl);
            bool yv1 = ((unsigned)y1 < (unsigned)Wl);

            float w00 = (1.f - fx) * (1.f - fy) * aw;
            float w10 = fx * (1.f - fy) * aw;
            float w01 = (1.f - fx) * fy * aw;
            float w11 = fx * fy * aw;

            int4 I;
            float4 Wv;
            I.x = (xv0 & yv0) ? start + y0 * Wl + x0 : start;
            I.y = (xv1 & yv0) ? start + y0 * Wl + x1 : start;
            I.z = (xv0 & yv1) ? start + y1 * Wl + x0 : start;
            I.w = (xv1 & yv1) ? start + y1 * Wl + x1 : start;
            Wv.x = (xv0 & yv0) ? w00 : 0.f;
            Wv.y = (xv1 & yv0) ? w10 : 0.f;
            Wv.z = (xv0 & yv1) ? w01 : 0.f;
            Wv.w = (xv1 & yv1) ? w11 : 0.f;

            g_idx4[(size_t)(bq0 + r) * 128 + t] = I;
            g_w4[(size_t)(bq0 + r) * 128 + t]   = Wv;
        }
    }
}

// ---------------------------------------------------------------------------
// Kernel 2: pure gather + weighted accumulate.
// Block = 256 threads = one (b,q); warp = head; lane = head-dim element.
// ---------------------------------------------------------------------------
__global__ __launch_bounds__(256) void dfine_k2(
    const float* __restrict__ enc,     // (B, S, C)
    float* __restrict__ out)           // (B,Q,C)
{
    const int bq   = blockIdx.x;
    const int h    = threadIdx.x >> 5;
    const int lane = threadIdx.x & 31;
    const int b    = bq / QQ;

    const float* vbase = enc + (size_t)b * SS * CC + h * DHH + lane;
    const int4*   ip = g_idx4 + (size_t)bq * 128 + h * 16;
    const float4* wp = g_w4   + (size_t)bq * 128 + h * 16;

    float acc = 0.f;
#pragma unroll
    for (int p = 0; p < SUMP; p++) {
        int4   I  = ip[p];
        float4 Wv = wp[p];
        acc = fmaf(Wv.x, __ldg(vbase + (size_t)I.x * CC), acc);
        acc = fmaf(Wv.y, __ldg(vbase + (size_t)I.y * CC), acc);
        acc = fmaf(Wv.z, __ldg(vbase + (size_t)I.z * CC), acc);
        acc = fmaf(Wv.w, __ldg(vbase + (size_t)I.w * CC), acc);
    }

    out[(size_t)bq * CC + h * DHH + lane] = acc;
}

// ---------------------------------------------------------------------------
// Launch. Inputs in metadata order; output = out(B,Q,C) flat, then attn
// (B,Q,NH,SUMP) flat.
// ---------------------------------------------------------------------------
extern "C" void kernel_launch(void* const* d_in, const int* in_sizes, int n_in,
                              void* d_out, int out_size) {
    const float* hs    = (const float*)d_in[0];
    const float* enc   = (const float*)d_in[1];
    const float* refp  = (const float*)d_in[2];
    const float* offk  = (const float*)d_in[3];
    const float* offb  = (const float*)d_in[4];
    const float* attnk = (const float*)d_in[5];
    const float* attnb = (const float*)d_in[6];
    const float* nps   = (const float*)d_in[7];

    float* out      = (float*)d_out;
    float* attn_out = out + (size_t)BQ * CC;

    dfine_k1<<<BQ / 16, 384>>>(hs, refp, offk, offb, attnk, attnb, nps, attn_out);
    dfine_k2<<<BQ, 256>>>(enc, out);
}

// round 3
// speedup vs baseline: 1.4034x; 1.4034x over previous
#include <cuda_runtime.h>
#include <math.h>

// Problem constants (fixed by the reference)
#define BB 16
#define QQ 300
#define CC 256
#define NHH 8
#define DHH 32
#define SUMP 16
#define SS 8500           // 80*80+40*40+20*20+10*10
#define BQ (BB*QQ)        // 4800

// scratch: sampling locations (B*Q, NH*SUMP*2)
__device__ float g_loc[BQ * 256];

__device__ __constant__ int cW[4]     = {80, 40, 20, 10};
__device__ __constant__ int cStart[4] = {0, 6400, 8000, 8400};

// ---------------------------------------------------------------------------
// Kernel 1: GEMM (4800x256)x(256x384) with packed f32x2 FMAs.
// Grid = 900 blocks: rt = bx/3 selects 16 rows, g = bx%3 selects 128 cols
//   (g=0,1 -> offset cols [g*128,g*128+128), g=2 -> all 128 attn cols).
// Block = 128 threads, each thread = one output column x 16 rows.
// ---------------------------------------------------------------------------
__global__ __launch_bounds__(128, 6) void dfine_k1(
    const float* __restrict__ hs,      // (B,Q,C)
    const float* __restrict__ refp,    // (B,Q,1,4)
    const float* __restrict__ offk,    // (C, 256) col-stride 256
    const float* __restrict__ offb,    // (256,)
    const float* __restrict__ attnk,   // (C, 128) col-stride 128
    const float* __restrict__ attnb,   // (128,)
    const float* __restrict__ nps,     // (SUMP,)
    float* __restrict__ attn_out)      // (B,Q,NH,SUMP) region of d_out
{
    __shared__ __align__(16) float sAT[CC][20];  // A transposed, padded
    __shared__ float sL[16][128];                // logits (g==2 only)

    const int t   = threadIdx.x;        // 0..127
    const int g   = blockIdx.x % 3;     // col group
    const int rt  = blockIdx.x / 3;     // row tile
    const int bq0 = rt * 16;

    // load 16 rows of hidden_states, transposed, into smem (float4 GMEM reads)
    {
        const float4* src = (const float4*)(hs + (size_t)bq0 * CC);
        for (int i4 = t; i4 < 16 * CC / 4; i4 += 128) {
            float4 v = src[i4];
            const int r = i4 >> 6;          // i4*4 >> 8
            const int c = (i4 << 2) & 255;
            sAT[c][r]     = v.x;
            sAT[c + 1][r] = v.y;
            sAT[c + 2][r] = v.z;
            sAT[c + 3][r] = v.w;
        }
    }
    __syncthreads();

    // ---- GEMM: 16-row accumulators as 8 packed f32x2 pairs ----
    unsigned long long acc[8];
#pragma unroll
    for (int j = 0; j < 8; j++) acc[j] = 0ULL;

    {
        const float* col = (g == 2) ? (attnk + t) : (offk + g * 128 + t);
        const int stride = (g == 2) ? 128 : 256;
#pragma unroll 4
        for (int c = 0; c < CC; c++) {
            float bv = __ldg(col + (size_t)c * stride);
            unsigned long long bb;
            asm("mov.b64 %0, {%1, %1};" : "=l"(bb) : "r"(__float_as_uint(bv)));
#pragma unroll
            for (int i = 0; i < 4; i++) {
                ulonglong2 v = *(const ulonglong2*)&sAT[c][4 * i];
                asm("fma.rn.f32x2 %0, %1, %2, %0;" : "+l"(acc[2*i])   : "l"(v.x), "l"(bb));
                asm("fma.rn.f32x2 %0, %1, %2, %0;" : "+l"(acc[2*i+1]) : "l"(v.y), "l"(bb));
            }
        }
    }

    // unpack accumulators -> per-row scalars
    float o[16];
#pragma unroll
    for (int j = 0; j < 8; j++) {
        unsigned u0, u1;
        asm("mov.b64 {%0, %1}, %2;" : "=r"(u0), "=r"(u1) : "l"(acc[j]));
        o[2*j]   = __uint_as_float(u0);
        o[2*j+1] = __uint_as_float(u1);
    }

    if (g < 2) {
        // offset path: bias, scale by nps*wh*0.5, add center -> g_loc
        const int j     = g * 128 + t;      // 0..255
        const int axis  = j & 1;
        const int p     = (j >> 1) & 15;
        const float bias  = offb[j];
        const float scale = nps[p] * 0.5f;
#pragma unroll
        for (int r = 0; r < 16; r++) {
            const float* rp = refp + (size_t)(bq0 + r) * 4;
            g_loc[(size_t)(bq0 + r) * 256 + j] =
                fmaf((o[r] + bias) * scale, rp[2 + axis], rp[axis]);
        }
    } else {
        // attn path: bias -> smem logits, softmax over 16-point head group
        const float bias = attnb[t];
#pragma unroll
        for (int r = 0; r < 16; r++) sL[r][t] = o[r] + bias;
        __syncthreads();

        const int base = (t >> 4) << 4;
#pragma unroll
        for (int r = 0; r < 16; r++) {
            float m = -1e30f;
#pragma unroll
            for (int p = 0; p < 16; p++) m = fmaxf(m, sL[r][base + p]);
            float s = 0.f;
#pragma unroll
            for (int p = 0; p < 16; p++) s += __expf(sL[r][base + p] - m);
            attn_out[(size_t)(bq0 + r) * 128 + t] = __expf(sL[r][t] - m) / s;
        }
    }
}

// ---------------------------------------------------------------------------
// Kernel 2: per-query gather + weighted accumulate.
// Block = 256 threads = one (b,q). Phase 1: threads 0..127 build gather
// descriptors (clamped indices + attn-premultiplied bilinear weights) in smem.
// Phase 2: warp = head, lane = head-dim element; 64 gathers per warp.
// ---------------------------------------------------------------------------
__global__ __launch_bounds__(256) void dfine_k2(
    const float* __restrict__ enc,     // (B, S, C)
    const float* __restrict__ attn,    // (B,Q,NH,SUMP)
    float* __restrict__ out)           // (B,Q,C)
{
    __shared__ int4   sI[128];
    __shared__ float4 sWt[128];

    const int bq = blockIdx.x;
    const int t  = threadIdx.x;
    const int b  = bq / QQ;

    if (t < 128) {
        const int h   = t >> 4;
        const int p   = t & 15;
        const int lvl = p >> 2;
        const int Wl    = cW[lvl];
        const int start = cStart[lvl];
        const float Wf  = (float)Wl;

        float lx = g_loc[(size_t)bq * 256 + h * 32 + p * 2];
        float ly = g_loc[(size_t)bq * 256 + h * 32 + p * 2 + 1];
        float aw = attn[(size_t)bq * 128 + t];

        float x = lx * Wf - 0.5f;
        float y = ly * Wf - 0.5f;
        float x0f = floorf(x), y0f = floorf(y);
        float fx = x - x0f, fy = y - y0f;
        int x0 = (int)x0f, y0 = (int)y0f;
        int x1 = x0 + 1,   y1 = y0 + 1;

        bool xv0 = ((unsigned)x0 < (unsigned)Wl);
        bool xv1 = ((unsigned)x1 < (unsigned)Wl);
        bool yv0 = ((unsigned)y0 < (unsigned)Wl);
        bool yv1 = ((unsigned)y1 < (unsigned)Wl);

        float w00 = (1.f - fx) * (1.f - fy) * aw;
        float w10 = fx * (1.f - fy) * aw;
        float w01 = (1.f - fx) * fy * aw;
        float w11 = fx * fy * aw;

        int4 I; float4 Wv;
        I.x = (xv0 & yv0) ? start + y0 * Wl + x0 : start;
        I.y = (xv1 & yv0) ? start + y0 * Wl + x1 : start;
        I.z = (xv0 & yv1) ? start + y1 * Wl + x0 : start;
        I.w = (xv1 & yv1) ? start + y1 * Wl + x1 : start;
        Wv.x = (xv0 & yv0) ? w00 : 0.f;
        Wv.y = (xv1 & yv0) ? w10 : 0.f;
        Wv.z = (xv0 & yv1) ? w01 : 0.f;
        Wv.w = (xv1 & yv1) ? w11 : 0.f;

        sI[t]  = I;
        sWt[t] = Wv;
    }
    __syncthreads();

    const int h    = t >> 5;
    const int lane = t & 31;
    const float* vbase = enc + (size_t)b * SS * CC + h * DHH + lane;

    float acc = 0.f;
#pragma unroll
    for (int p = 0; p < SUMP; p++) {
        int4   I  = sI[h * 16 + p];
        float4 Wv = sWt[h * 16 + p];
        acc = fmaf(Wv.x, __ldg(vbase + (size_t)I.x * CC), acc);
        acc = fmaf(Wv.y, __ldg(vbase + (size_t)I.y * CC), acc);
        acc = fmaf(Wv.z, __ldg(vbase + (size_t)I.z * CC), acc);
        acc = fmaf(Wv.w, __ldg(vbase + (size_t)I.w * CC), acc);
    }

    out[(size_t)bq * CC + h * DHH + lane] = acc;
}

// ---------------------------------------------------------------------------
// Launch. Inputs in metadata order; output = out(B,Q,C) flat, then attn
// (B,Q,NH,SUMP) flat.
// ---------------------------------------------------------------------------
extern "C" void kernel_launch(void* const* d_in, const int* in_sizes, int n_in,
                              void* d_out, int out_size) {
    const float* hs    = (const float*)d_in[0];
    const float* enc   = (const float*)d_in[1];
    const float* refp  = (const float*)d_in[2];
    const float* offk  = (const float*)d_in[3];
    const float* offb  = (const float*)d_in[4];
    const float* attnk = (const float*)d_in[5];
    const float* attnb = (const float*)d_in[6];
    const float* nps   = (const float*)d_in[7];

    float* out      = (float*)d_out;
    float* attn_out = out + (size_t)BQ * CC;

    dfine_k1<<<900, 128>>>(hs, refp, offk, offb, attnk, attnb, nps, attn_out);
    dfine_k2<<<BQ, 256>>>(enc, attn_out, out);
}